// round 10
// baseline (speedup 1.0000x reference)
#include <cuda_runtime.h>
#include <cuda_fp16.h>
#include <cstdint>

#define N_NODES 8192
#define M_NBR   16
#define F_NODE  128
#define HID     512

// ---------------- scratch (__device__ globals; no allocations) ----------------
__device__ __half g_HA[N_NODES * HID];   // activation ping
__device__ __half g_HB[N_NODES * HID];   // activation pong
__device__ float  g_dinv[N_NODES];
#define WOFF_1 0
#define WOFF_2 (HID * HID)
#define WOFF_3 (2 * HID * HID)
#define WOFF_E (3 * HID * HID)
__device__ __half g_W[3 * HID * HID + HID * F_NODE];

// ---------------- PTX helpers (compute_103-safe) ----------------
__device__ __forceinline__ uint32_t smem_to_u32(const void* p) {
    uint32_t a;
    asm("{ .reg .u64 t; cvta.to.shared.u64 t, %1; cvt.u32.u64 %0, t; }" : "=r"(a) : "l"(p));
    return a;
}
__device__ __forceinline__ void cp_async16(uint32_t saddr, const void* gptr) {
    asm volatile("cp.async.cg.shared.global [%0], [%1], 16;" :: "r"(saddr), "l"(gptr));
}
#define CP_COMMIT() asm volatile("cp.async.commit_group;" ::: "memory")
#define CP_WAIT0()  asm volatile("cp.async.wait_group 0;" ::: "memory")
#define CP_WAIT1()  asm volatile("cp.async.wait_group 1;" ::: "memory")

__device__ __forceinline__ void ldsm_x4(uint32_t& r0, uint32_t& r1, uint32_t& r2,
                                        uint32_t& r3, uint32_t addr) {
    asm volatile("ldmatrix.sync.aligned.m8n8.x4.shared.b16 {%0,%1,%2,%3}, [%4];"
                 : "=r"(r0), "=r"(r1), "=r"(r2), "=r"(r3) : "r"(addr));
}
__device__ __forceinline__ void mma16816(float* d, const uint32_t* a, const uint32_t* b) {
    asm volatile(
        "mma.sync.aligned.m16n8k16.row.col.f32.f16.f16.f32 "
        "{%0,%1,%2,%3}, {%4,%5,%6,%7}, {%8,%9}, {%0,%1,%2,%3};"
        : "+f"(d[0]), "+f"(d[1]), "+f"(d[2]), "+f"(d[3])
        : "r"(a[0]), "r"(a[1]), "r"(a[2]), "r"(a[3]), "r"(b[0]), "r"(b[1]));
}

// ---------------------------------------------------------------------------
// Fused preprocessing (one launch)
// ---------------------------------------------------------------------------
#define PREP_DEG    32
#define PREP_CONV   1024
#define PREP_WE     64
#define PREP_W3     768
#define PREP_BLOCKS (PREP_DEG + PREP_CONV + PREP_WE + PREP_W3)

__device__ __forceinline__ void wconv_tile(const float* __restrict__ W, int K, int N,
                                           __half* __restrict__ o,
                                           int n0, int k0, int tx, int ty,
                                           float (*tile)[33]) {
#pragma unroll
    for (int r = 0; r < 4; r++) {
        int k = k0 + ty + r * 8;
        tile[ty + r * 8][tx] = W[(size_t)k * N + n0 + tx];
    }
    __syncthreads();
#pragma unroll
    for (int r = 0; r < 4; r++) {
        int n = ty + r * 8;
        o[(size_t)(n0 + n) * K + k0 + tx] = __float2half_rn(tile[tx][n]);
    }
}

__global__ __launch_bounds__(256) void prep_kernel(const int* __restrict__ idx,
                                                   const float* __restrict__ node_in,
                                                   const float* __restrict__ W_emb,
                                                   const float* __restrict__ W1,
                                                   const float* __restrict__ W2,
                                                   const float* __restrict__ W3) {
    __shared__ float tile[32][33];
    const int b = blockIdx.x;
    const int tid = threadIdx.x;

    if (b < PREP_DEG) {
        int i = b * 256 + tid;
        int cnt = 1;
#pragma unroll
        for (int k = 0; k < M_NBR; k++) cnt += (idx[i * M_NBR + k] >= 0) ? 1 : 0;
        g_dinv[i] = rsqrtf((float)cnt);
    } else if (b < PREP_DEG + PREP_CONV) {
        int c4 = (b - PREP_DEG) * 256 + tid;
        float4 v = ((const float4*)node_in)[c4];
        __half2 h0 = __floats2half2_rn(v.x, v.y);
        __half2 h1 = __floats2half2_rn(v.z, v.w);
        uint2 o;
        o.x = *(uint32_t*)&h0;
        o.y = *(uint32_t*)&h1;
        ((uint2*)g_HA)[c4] = o;
    } else if (b < PREP_DEG + PREP_CONV + PREP_WE) {
        int t = b - (PREP_DEG + PREP_CONV);
        int n0 = (t & 15) * 32, k0 = (t >> 4) * 32;
        wconv_tile(W_emb, F_NODE, HID, g_W + WOFF_E, n0, k0, tid & 31, tid >> 5, tile);
    } else {
        int t = b - (PREP_DEG + PREP_CONV + PREP_WE);
        int z = t >> 8;
        int tt = t & 255;
        int n0 = (tt & 15) * 32, k0 = (tt >> 4) * 32;
        const float* W = (z == 0) ? W1 : (z == 1) ? W2 : W3;
        wconv_tile(W, HID, HID, g_W + (size_t)z * HID * HID, n0, k0,
                   tid & 31, tid >> 5, tile);
    }
}

// ---------------------------------------------------------------------------
// SpMM (fp16 in/out, fp32 accumulate), branch-free gathers.
// ---------------------------------------------------------------------------
__global__ __launch_bounds__(256) void spmm_kernel(const int* __restrict__ idx,
                                                   const __half* __restrict__ Xin,
                                                   __half* __restrict__ Xout) {
    const int rloc = threadIdx.x >> 6;
    const int t64 = threadIdx.x & 63;
    const int i = blockIdx.x * 4 + rloc;

    __shared__ int s_j[4][M_NBR];
    __shared__ float s_dj[4][M_NBR];
    if (t64 < M_NBR) {
        int j = idx[i * M_NBR + t64];
        s_j[rloc][t64] = (j >= 0) ? j : 0;
        s_dj[rloc][t64] = (j >= 0) ? g_dinv[j] : 0.0f;
    }
    __syncthreads();

    const float di = g_dinv[i];
    float acc[8];
    {
        uint4 v = ((const uint4*)(Xin + (size_t)i * HID))[t64];
        float2 p0 = __half22float2(*(__half2*)&v.x);
        float2 p1 = __half22float2(*(__half2*)&v.y);
        float2 p2 = __half22float2(*(__half2*)&v.z);
        float2 p3 = __half22float2(*(__half2*)&v.w);
        acc[0] = p0.x * di; acc[1] = p0.y * di;
        acc[2] = p1.x * di; acc[3] = p1.y * di;
        acc[4] = p2.x * di; acc[5] = p2.y * di;
        acc[6] = p3.x * di; acc[7] = p3.y * di;
    }

#pragma unroll
    for (int k = 0; k < M_NBR; k++) {
        const int j = s_j[rloc][k];
        const float dj = s_dj[rloc][k];
        uint4 v = ((const uint4*)(Xin + (size_t)j * HID))[t64];
        float2 p0 = __half22float2(*(__half2*)&v.x);
        float2 p1 = __half22float2(*(__half2*)&v.y);
        float2 p2 = __half22float2(*(__half2*)&v.z);
        float2 p3 = __half22float2(*(__half2*)&v.w);
        acc[0] += dj * p0.x; acc[1] += dj * p0.y;
        acc[2] += dj * p1.x; acc[3] += dj * p1.y;
        acc[4] += dj * p2.x; acc[5] += dj * p2.y;
        acc[6] += dj * p3.x; acc[7] += dj * p3.y;
    }

    uint4 o;
    __half2 h0 = __floats2half2_rn(acc[0] * di, acc[1] * di);
    __half2 h1 = __floats2half2_rn(acc[2] * di, acc[3] * di);
    __half2 h2 = __floats2half2_rn(acc[4] * di, acc[5] * di);
    __half2 h3 = __floats2half2_rn(acc[6] * di, acc[7] * di);
    o.x = *(uint32_t*)&h0;
    o.y = *(uint32_t*)&h1;
    o.z = *(uint32_t*)&h2;
    o.w = *(uint32_t*)&h3;
    ((uint4*)(Xout + (size_t)i * HID))[t64] = o;
}

// ---------------------------------------------------------------------------
// fp16 HMMA GEMM: C[M x 512] = A[M x K] * B[512 x K]^T + bias (+relu)
// BM=128 BN=256 BK=64, 256 thr, warp grid 2x4, warp tile 64x64,
// 3-stage cp.async, one __syncthreads per k-iter, 144 B smem rows.
// ---------------------------------------------------------------------------
#define BM 128
#define BN 256
#define BK 64
#define GTHR 256
#define ROWB 144                       // 64*2 + 16 pad bytes
#define STAGE_B ((BM + BN) * ROWB)     // 55296 B per stage
#define GSMEM   (3 * STAGE_B)          // 165888 B

template <int K, bool HALF_OUT>
__global__ __launch_bounds__(GTHR, 1)
void gemm_hmma_kernel(const __half* __restrict__ A,
                      const __half* __restrict__ B,
                      const float* __restrict__ bias,
                      void* __restrict__ Cout, int relu) {
    extern __shared__ __align__(16) char dynsmem[];

    const int tid = threadIdx.x;
    const int lane = tid & 31;
    const int wid = tid >> 5;
    const int warp_m = wid >> 2;   // 0..1  (64-row band)
    const int warp_n = wid & 3;    // 0..3  (64-col band)
    const int m0 = blockIdx.y * BM;
    const int n0 = blockIdx.x * BN;

    uint32_t sA[3], sB[3];
#pragma unroll
    for (int s = 0; s < 3; s++) {
        sA[s] = smem_to_u32(dynsmem + s * STAGE_B);
        sB[s] = sA[s] + BM * ROWB;
    }

    // acc[mt][nt][4]: mt 0..3 (16-row frags), nt 0..7 (8-col frags) = 128 regs
    float acc[4][8][4];
#pragma unroll
    for (int i = 0; i < 4; i++)
#pragma unroll
        for (int j = 0; j < 8; j++)
#pragma unroll
            for (int q = 0; q < 4; q++) acc[i][j][q] = 0.0f;

    constexpr int KT = K / BK;

    const int mat = lane >> 3;
    const int mrow = lane & 7;
    const int a_row = warp_m * 64 + ((mat & 1) << 3) + mrow;
    const int a_koff = (mat >> 1) << 3;
    const int b_row = warp_n * 64 + ((mat >> 1) << 3) + mrow;
    const int b_koff = (mat & 1) << 3;

    // loads: A 128 rows x 8 chunks = 1024 (4/thr); B 256 x 8 = 2048 (8/thr)
    const int lr = tid >> 3;        // 0..31
    const int lc = tid & 7;         // 0..7

#define LOAD_STAGE(kt, buf)                                                     \
    do {                                                                        \
        const int kk_ = (kt) * BK;                                              \
        _Pragma("unroll")                                                       \
        for (int s_ = 0; s_ < 4; s_++) {                                        \
            int r_ = lr + s_ * 32;                                              \
            cp_async16(sA[buf] + r_ * ROWB + lc * 16,                           \
                       A + (size_t)(m0 + r_) * K + kk_ + lc * 8);               \
        }                                                                       \
        _Pragma("unroll")                                                       \
        for (int s_ = 0; s_ < 8; s_++) {                                        \
            int r_ = lr + s_ * 32;                                              \
            cp_async16(sB[buf] + r_ * ROWB + lc * 16,                           \
                       B + (size_t)(n0 + r_) * K + kk_ + lc * 8);               \
        }                                                                       \
    } while (0)

    LOAD_STAGE(0, 0);
    CP_COMMIT();
    LOAD_STAGE(1, 1);
    CP_COMMIT();

    for (int kt = 0; kt < KT; kt++) {
        const int buf = kt % 3;
        if (kt + 1 < KT) CP_WAIT1(); else CP_WAIT0();
        __syncthreads();
        if (kt + 2 < KT) {
            LOAD_STAGE(kt + 2, (kt + 2) % 3);
            CP_COMMIT();
        }

#pragma unroll
        for (int ks = 0; ks < BK / 16; ks++) {
            uint32_t af[4][4];
#pragma unroll
            for (int mt = 0; mt < 4; mt++) {
                uint32_t addr = sA[buf] + (a_row + mt * 16) * ROWB +
                                (ks * 16 + a_koff) * 2;
                ldsm_x4(af[mt][0], af[mt][1], af[mt][2], af[mt][3], addr);
            }
            // B: 4 p-groups of 16 rows; only 4 B regs live at a time
#pragma unroll
            for (int p = 0; p < 4; p++) {
                uint32_t r0, r1, r2, r3;
                uint32_t addr = sB[buf] + (b_row + p * 16) * ROWB +
                                (ks * 16 + b_koff) * 2;
                ldsm_x4(r0, r1, r2, r3, addr);
                uint32_t b0[2] = {r0, r1};
                uint32_t b1[2] = {r2, r3};
#pragma unroll
                for (int mt = 0; mt < 4; mt++) {
                    mma16816(acc[mt][2 * p], af[mt], b0);
                    mma16816(acc[mt][2 * p + 1], af[mt], b1);
                }
            }
        }
    }

    // epilogue
#pragma unroll
    for (int mt = 0; mt < 4; mt++) {
        const int rm = m0 + warp_m * 64 + mt * 16 + (lane >> 2);
#pragma unroll
        for (int nt = 0; nt < 8; nt++) {
            const int cn = n0 + warp_n * 64 + nt * 8 + ((lane & 3) << 1);
            const float b0 = bias[cn], b1 = bias[cn + 1];
            float2 v0, v1;
            v0.x = acc[mt][nt][0] + b0;
            v0.y = acc[mt][nt][1] + b1;
            v1.x = acc[mt][nt][2] + b0;
            v1.y = acc[mt][nt][3] + b1;
            if (relu) {
                v0.x = fmaxf(v0.x, 0.0f); v0.y = fmaxf(v0.y, 0.0f);
                v1.x = fmaxf(v1.x, 0.0f); v1.y = fmaxf(v1.y, 0.0f);
            }
            if (HALF_OUT) {
                __half* Ch = (__half*)Cout;
                *(__half2*)&Ch[(size_t)rm * HID + cn] = __floats2half2_rn(v0.x, v0.y);
                *(__half2*)&Ch[(size_t)(rm + 8) * HID + cn] = __floats2half2_rn(v1.x, v1.y);
            } else {
                float* Cf = (float*)Cout;
                *(float2*)&Cf[(size_t)rm * HID + cn] = v0;
                *(float2*)&Cf[(size_t)(rm + 8) * HID + cn] = v1;
            }
        }
    }
}

// ---------------------------------------------------------------------------
extern "C" void kernel_launch(void* const* d_in, const int* in_sizes, int n_in,
                              void* d_out, int out_size) {
    const float* node_in = (const float*)d_in[0];
    const int*   edges   = (const int*)d_in[1];
    const float* W_emb   = (const float*)d_in[2];
    const float* b_emb   = (const float*)d_in[3];
    const float* W1      = (const float*)d_in[4];
    const float* b1      = (const float*)d_in[5];
    const float* W2      = (const float*)d_in[6];
    const float* b2      = (const float*)d_in[7];
    const float* W3      = (const float*)d_in[8];
    const float* b3      = (const float*)d_in[9];
    float* out = (float*)d_out;

    __half* HA; cudaGetSymbolAddress((void**)&HA, g_HA);
    __half* HB; cudaGetSymbolAddress((void**)&HB, g_HB);
    __half* W;  cudaGetSymbolAddress((void**)&W, g_W);

    cudaFuncSetAttribute(gemm_hmma_kernel<HID, true>,
                         cudaFuncAttributeMaxDynamicSharedMemorySize, GSMEM);
    cudaFuncSetAttribute(gemm_hmma_kernel<HID, false>,
                         cudaFuncAttributeMaxDynamicSharedMemorySize, GSMEM);
    cudaFuncSetAttribute(gemm_hmma_kernel<F_NODE, true>,
                         cudaFuncAttributeMaxDynamicSharedMemorySize, GSMEM);

    prep_kernel<<<PREP_BLOCKS, 256>>>(edges, node_in, W_emb, W1, W2, W3);

    dim3 gg(HID / BN, N_NODES / BM);  // (2, 64) = 128 CTAs

    // embed: HB = node_in @ W_emb + b_emb  (fp16 out)
    gemm_hmma_kernel<F_NODE, true><<<gg, GTHR, GSMEM>>>(HA, W + WOFF_E, b_emb, HB, 0);
    // layer 1
    spmm_kernel<<<N_NODES / 4, 256>>>(edges, HB, HA);
    gemm_hmma_kernel<HID, true><<<gg, GTHR, GSMEM>>>(HA, W + WOFF_1, b1, HB, 1);
    // layer 2
    spmm_kernel<<<N_NODES / 4, 256>>>(edges, HB, HA);
    gemm_hmma_kernel<HID, true><<<gg, GTHR, GSMEM>>>(HA, W + WOFF_2, b2, HB, 1);
    // layer 3 -> fp32 out
    spmm_kernel<<<N_NODES / 4, 256>>>(edges, HB, HA);
    gemm_hmma_kernel<HID, false><<<gg, GTHR, GSMEM>>>(HA, W + WOFF_3, b3, out, 0);
}